// round 2
// baseline (speedup 1.0000x reference)
#include <cuda_runtime.h>
#include <cuda_bf16.h>

// RoiPoolingConv: crop + bilinear resize (tf.image.resize_images semantics,
// align_corners=False: src = dst * in/out, edge-clamped).
// img:  [1, 128, 128, 512] float32 (NHWC)
// rois: [1000, 4] int32  (x1, y1, x2, y2), SCALE=1.0
// out:  [1000, 14, 14, 512] float32
//
// R2: rolling register cache of the 4 corner vectors. Column indices are
// uniform per block and non-decreasing in px, so consecutive px iterations
// share columns (cl==old cr, cr==cl, etc). Only genuinely new columns hit
// L1 — cuts L1 load traffic ~1.7x (the R1 bottleneck at 78% L1 SOL).

#define PH 14
#define PW 14
#define IMG_W 128
#define NCH 512
#define NV4 (NCH / 4)   // 128 float4 per pixel

__global__ __launch_bounds__(NV4)
void roi_pool_kernel(const float4* __restrict__ img,
                     const int4* __restrict__ rois,
                     float4* __restrict__ out) {
    const int py = blockIdx.x;     // 0..13
    const int n  = blockIdx.y;     // roi index
    const int t  = threadIdx.x;    // 0..127 (float4 lane)

    const int4 r = rois[n];
    const int x0 = r.x;
    const int y0 = r.y;
    const int in_w = r.z - r.x + 1;
    const int in_h = r.w - r.y + 1;

    // Match reference float order: sy = py * (in_h / PH)
    const float fy = (float)py * ((float)in_h / (float)PH);
    const int yt = (int)floorf(fy);
    const int yb = min(yt + 1, in_h - 1);
    const float wy = fy - (float)yt;

    const float4* __restrict__ pT = img + (size_t)((y0 + yt) * IMG_W) * NV4 + t;
    const float4* __restrict__ pB = img + (size_t)((y0 + yb) * IMG_W) * NV4 + t;
    const float sxw = (float)in_w / (float)PW;

    float4* outp = out + (((size_t)n * PH + py) * PW) * NV4 + t;

    // Rolling corner cache (indices uniform across block -> no divergence)
    int ocl = -1, ocr = -1;
    float4 vTl, vTr, vBl, vBr;

    #pragma unroll
    for (int px = 0; px < PW; ++px) {
        const float fx = (float)px * sxw;
        const int xt = (int)floorf(fx);
        const int xr = min(xt + 1, in_w - 1);
        const float wx = fx - (float)xt;
        const int cl = x0 + xt;
        const int cr = x0 + xr;

        float4 nTl, nTr, nBl, nBr;
        // left column
        if (cl == ocl)      { nTl = vTl; nBl = vBl; }
        else if (cl == ocr) { nTl = vTr; nBl = vBr; }
        else {
            nTl = __ldg(pT + (size_t)cl * NV4);
            nBl = __ldg(pB + (size_t)cl * NV4);
        }
        // right column (cr >= cl; cr is either cl, old cr, or new)
        if (cr == cl)       { nTr = nTl; nBr = nBl; }
        else if (cr == ocr) { nTr = vTr; nBr = vBr; }
        else {
            nTr = __ldg(pT + (size_t)cr * NV4);
            nBr = __ldg(pB + (size_t)cr * NV4);
        }
        vTl = nTl; vTr = nTr; vBl = nBl; vBr = nBr;
        ocl = cl; ocr = cr;

        float4 o;
        {
            float top, bot;
            top = vTl.x + wx * (vTr.x - vTl.x);
            bot = vBl.x + wx * (vBr.x - vBl.x);
            o.x = top + wy * (bot - top);
            top = vTl.y + wx * (vTr.y - vTl.y);
            bot = vBl.y + wx * (vBr.y - vBl.y);
            o.y = top + wy * (bot - top);
            top = vTl.z + wx * (vTr.z - vTl.z);
            bot = vBl.z + wx * (vBr.z - vBl.z);
            o.z = top + wy * (bot - top);
            top = vTl.w + wx * (vTr.w - vTl.w);
            bot = vBl.w + wx * (vBr.w - vBl.w);
            o.w = top + wy * (bot - top);
        }
        outp[(size_t)px * NV4] = o;
    }
}

extern "C" void kernel_launch(void* const* d_in, const int* in_sizes, int n_in,
                              void* d_out, int out_size) {
    const float4* img  = (const float4*)d_in[0];
    const int4*   rois = (const int4*)d_in[1];
    float4*       out  = (float4*)d_out;

    const int n_rois = in_sizes[1] / 4;   // 1000

    dim3 grid(PH, n_rois);
    dim3 block(NV4);
    roi_pool_kernel<<<grid, block>>>(img, rois, out);
}

// round 4
// speedup vs baseline: 1.0312x; 1.0312x over previous
#include <cuda_runtime.h>
#include <cuda_bf16.h>

// RoiPoolingConv: crop + bilinear resize (tf.image.resize_images semantics,
// align_corners=False: src = dst * in/out, edge-clamped).
// img:  [1, 128, 128, 512] float32 (NHWC)
// rois: [1000, 4] int32  (x1, y1, x2, y2), SCALE=1.0
// out:  [1000, 14, 14, 512] float32
//
// R3: specialize the px-loop on in_w (compile-time W, 31-way switch).
// Column offsets become constants -> duplicate __ldg's to the same address
// are CSE'd by the compiler: one load per unique column (avg ~17 vs 28),
// unconditional, branch-free, hoisted for max MLP. This removes the L1
// traffic that bound R1 (78% L1 SOL) without R2's branch serialization.

#define PH 14
#define PW 14
#define IMG_W 128
#define NCH 512
#define NV4 (NCH / 4)   // 128 float4 per pixel

__device__ __forceinline__ void lerp_store(const float4 v00, const float4 v01,
                                           const float4 v10, const float4 v11,
                                           const float wx, const float wy,
                                           float4* __restrict__ dst) {
    float4 o;
    float top, bot;
    top = v00.x + wx * (v01.x - v00.x);
    bot = v10.x + wx * (v11.x - v10.x);
    o.x = top + wy * (bot - top);
    top = v00.y + wx * (v01.y - v00.y);
    bot = v10.y + wx * (v11.y - v10.y);
    o.y = top + wy * (bot - top);
    top = v00.z + wx * (v01.z - v00.z);
    bot = v10.z + wx * (v11.z - v10.z);
    o.z = top + wy * (bot - top);
    top = v00.w + wx * (v01.w - v00.w);
    bot = v10.w + wx * (v11.w - v10.w);
    o.w = top + wy * (bot - top);
    *dst = o;
}

// Compile-time-W row: all addresses constant -> load CSE, no branches.
template <int W>
__device__ __forceinline__ void pool_row(const float4* __restrict__ pT,
                                         const float4* __restrict__ pB,
                                         const float wy,
                                         float4* __restrict__ outp) {
    #pragma unroll
    for (int px = 0; px < PW; ++px) {
        const float fx = (float)px * ((float)W / 14.0f);  // folded, IEEE f32
        const int xt = (int)floorf(fx);                   // folded
        const int xr = min(xt + 1, W - 1);                // folded
        const float wx = fx - (float)xt;                  // folded

        const float4 v00 = __ldg(pT + xt * NV4);
        const float4 v01 = __ldg(pT + xr * NV4);
        const float4 v10 = __ldg(pB + xt * NV4);
        const float4 v11 = __ldg(pB + xr * NV4);
        lerp_store(v00, v01, v10, v11, wx, wy, outp + px * NV4);
    }
}

// Dynamic fallback (should not trigger for this dataset: in_w in [2,32]).
__device__ __forceinline__ void pool_row_dyn(const float4* __restrict__ pT,
                                             const float4* __restrict__ pB,
                                             const int in_w, const float wy,
                                             float4* __restrict__ outp) {
    const float sxw = (float)in_w / (float)PW;
    #pragma unroll
    for (int px = 0; px < PW; ++px) {
        const float fx = (float)px * sxw;
        const int xt = (int)floorf(fx);
        const int xr = min(xt + 1, in_w - 1);
        const float wx = fx - (float)xt;
        const float4 v00 = __ldg(pT + (size_t)xt * NV4);
        const float4 v01 = __ldg(pT + (size_t)xr * NV4);
        const float4 v10 = __ldg(pB + (size_t)xt * NV4);
        const float4 v11 = __ldg(pB + (size_t)xr * NV4);
        lerp_store(v00, v01, v10, v11, wx, wy, outp + px * NV4);
    }
}

__global__ __launch_bounds__(NV4, 8)
void roi_pool_kernel(const float4* __restrict__ img,
                     const int4* __restrict__ rois,
                     float4* __restrict__ out) {
    const int py = blockIdx.x;     // 0..13
    const int n  = blockIdx.y;     // roi index
    const int t  = threadIdx.x;    // 0..127 (float4 lane)

    const int4 r = __ldg(rois + n);
    const int x0 = r.x;
    const int y0 = r.y;
    const int in_w = r.z - r.x + 1;
    const int in_h = r.w - r.y + 1;

    // Vertical part (dynamic, matches reference f32 op order)
    const float fy = (float)py * ((float)in_h / (float)PH);
    const int yt = (int)floorf(fy);
    const int yb = min(yt + 1, in_h - 1);
    const float wy = fy - (float)yt;

    const float4* __restrict__ pT =
        img + ((size_t)((y0 + yt) * IMG_W + x0)) * NV4 + t;
    const float4* __restrict__ pB =
        img + ((size_t)((y0 + yb) * IMG_W + x0)) * NV4 + t;

    float4* outp = out + (((size_t)n * PH + py) * PW) * NV4 + t;

    switch (in_w) {
#define CASE_W(W_) case W_: pool_row<W_>(pT, pB, wy, outp); break;
        CASE_W(2)  CASE_W(3)  CASE_W(4)  CASE_W(5)  CASE_W(6)  CASE_W(7)
        CASE_W(8)  CASE_W(9)  CASE_W(10) CASE_W(11) CASE_W(12) CASE_W(13)
        CASE_W(14) CASE_W(15) CASE_W(16) CASE_W(17) CASE_W(18) CASE_W(19)
        CASE_W(20) CASE_W(21) CASE_W(22) CASE_W(23) CASE_W(24) CASE_W(25)
        CASE_W(26) CASE_W(27) CASE_W(28) CASE_W(29) CASE_W(30) CASE_W(31)
        CASE_W(32)
#undef CASE_W
        default: pool_row_dyn(pT, pB, in_w, wy, outp); break;
    }
}

extern "C" void kernel_launch(void* const* d_in, const int* in_sizes, int n_in,
                              void* d_out, int out_size) {
    const float4* img  = (const float4*)d_in[0];
    const int4*   rois = (const int4*)d_in[1];
    float4*       out  = (float4*)d_out;

    const int n_rois = in_sizes[1] / 4;   // 1000

    dim3 grid(PH, n_rois);
    dim3 block(NV4);
    roi_pool_kernel<<<grid, block>>>(img, rois, out);
}

// round 6
// speedup vs baseline: 1.1232x; 1.0891x over previous
#include <cuda_runtime.h>
#include <cuda_bf16.h>
#include <cstdint>

// RoiPoolingConv: crop + bilinear resize (tf.image.resize_images semantics,
// align_corners=False: src = dst * in/out, edge-clamped).
// img:  [1, 128, 128, 512] float32 (NHWC)
// rois: [1000, 4] int32  (x1, y1, x2, y2), SCALE=1.0
// out:  [1000, 14, 14, 512] float32
//
// R6: R1 structure (best so far, 90.2us) + cache-policy separation, fixed
// for ptxas: evict_last via createpolicy + L2::cache_hint (the direct
// .L2::evict_last qualifier on ld.v4.f32 is rejected on sm_103).
//   - image loads:  ld.global.nc.L2::cache_hint (policy = evict_last 1.0)
//   - output store: st.global.cs (streaming, evict-first)

#define PH 14
#define PW 14
#define IMG_W 128
#define NCH 512
#define NV4 (NCH / 4)   // 128 float4 per pixel

__device__ __forceinline__ float4 ldg_pin(const float4* p, uint64_t pol) {
    float4 v;
    asm volatile("ld.global.nc.L2::cache_hint.v4.f32 {%0,%1,%2,%3}, [%4], %5;"
                 : "=f"(v.x), "=f"(v.y), "=f"(v.z), "=f"(v.w)
                 : "l"(p), "l"(pol));
    return v;
}

__device__ __forceinline__ void stg_stream(float4* p, const float4 v) {
    asm volatile("st.global.cs.v4.f32 [%0], {%1,%2,%3,%4};"
                 :: "l"(p), "f"(v.x), "f"(v.y), "f"(v.z), "f"(v.w)
                 : "memory");
}

__global__ __launch_bounds__(NV4)
void roi_pool_kernel(const float4* __restrict__ img,
                     const int4* __restrict__ rois,
                     float4* __restrict__ out) {
    const int py = blockIdx.x;     // 0..13
    const int n  = blockIdx.y;     // roi index
    const int t  = threadIdx.x;    // 0..127 (float4 lane)

    uint64_t pol;
    asm volatile("createpolicy.fractional.L2::evict_last.b64 %0, 1.0;"
                 : "=l"(pol));

    const int4 r = __ldg(rois + n);
    const int x0 = r.x;
    const int y0 = r.y;
    const int in_w = r.z - r.x + 1;
    const int in_h = r.w - r.y + 1;

    // Match reference float order: sy = py * (in_h / PH)
    const float fy = (float)py * ((float)in_h / (float)PH);
    const int yt = (int)floorf(fy);
    const int yb = min(yt + 1, in_h - 1);
    const float wy = fy - (float)yt;

    const float4* __restrict__ pT =
        img + (size_t)((y0 + yt) * IMG_W + x0) * NV4 + t;
    const float4* __restrict__ pB =
        img + (size_t)((y0 + yb) * IMG_W + x0) * NV4 + t;
    const float sxw = (float)in_w / (float)PW;

    float4* outp = out + (((size_t)n * PH + py) * PW) * NV4 + t;

    #pragma unroll
    for (int px = 0; px < PW; ++px) {
        const float fx = (float)px * sxw;
        const int xt = (int)floorf(fx);
        const int xr = min(xt + 1, in_w - 1);
        const float wx = fx - (float)xt;

        const float4 v00 = ldg_pin(pT + (size_t)xt * NV4, pol);
        const float4 v01 = ldg_pin(pT + (size_t)xr * NV4, pol);
        const float4 v10 = ldg_pin(pB + (size_t)xt * NV4, pol);
        const float4 v11 = ldg_pin(pB + (size_t)xr * NV4, pol);

        float4 o;
        {
            float top, bot;
            top = v00.x + wx * (v01.x - v00.x);
            bot = v10.x + wx * (v11.x - v10.x);
            o.x = top + wy * (bot - top);
            top = v00.y + wx * (v01.y - v00.y);
            bot = v10.y + wx * (v11.y - v10.y);
            o.y = top + wy * (bot - top);
            top = v00.z + wx * (v01.z - v00.z);
            bot = v10.z + wx * (v11.z - v10.z);
            o.z = top + wy * (bot - top);
            top = v00.w + wx * (v01.w - v00.w);
            bot = v10.w + wx * (v11.w - v10.w);
            o.w = top + wy * (bot - top);
        }
        stg_stream(outp + (size_t)px * NV4, o);
    }
}

extern "C" void kernel_launch(void* const* d_in, const int* in_sizes, int n_in,
                              void* d_out, int out_size) {
    const float4* img  = (const float4*)d_in[0];
    const int4*   rois = (const int4*)d_in[1];
    float4*       out  = (float4*)d_out;

    const int n_rois = in_sizes[1] / 4;   // 1000

    dim3 grid(PH, n_rois);
    dim3 block(NV4);
    roi_pool_kernel<<<grid, block>>>(img, rois, out);
}